// round 13
// baseline (speedup 1.0000x reference)
#include <cuda_runtime.h>
#include <cstdint>

#define WINDOW 40
#define EE 8
#define NSTOCK 8000
#define TDIM 64
#define FDIM 64
#define INCH 144
#define LOUT 36

__device__ float g_xcol[WINDOW * EE * NSTOCK];      // [col][n]  staged slice
__device__ float g_rank[WINDOW * EE * NSTOCK];      // [col][n]
__device__ float g_rank_t[NSTOCK * WINDOW * EE];    // [n][col]

// ---------------------------------------------------------------------------
// Gather: x[:, 24:64, 0:8] -> g_xcol[col][n], full sector efficiency.
// ---------------------------------------------------------------------------
__global__ void __launch_bounds__(256) gather_kernel(const float* __restrict__ x) {
    __shared__ float tile[8][128];
    const int twv = blockIdx.x;
    const int n0 = blockIdx.y * 128;
    const int t = threadIdx.x;

    {
        int nl = t >> 1, half = t & 1;
        int n = n0 + nl;
        if (n < NSTOCK) {
            float4 v = *(const float4*)(x + (size_t)n * (TDIM * FDIM) + (24 + twv) * FDIM + half * 4);
            tile[half * 4 + 0][nl] = v.x;
            tile[half * 4 + 1][nl] = v.y;
            tile[half * 4 + 2][nl] = v.z;
            tile[half * 4 + 3][nl] = v.w;
        }
    }
    __syncthreads();
    {
        int idx = t * 4;
        int c = idx >> 7, nl = idx & 127;
        if (n0 + nl + 3 < NSTOCK) {
            float4 v = *(const float4*)(&tile[c][nl]);
            *(float4*)(g_xcol + (size_t)(twv * 8 + c) * NSTOCK + n0 + nl) = v;
        } else {
            for (int j = 0; j < 4; j++)
                if (n0 + nl + j < NSTOCK)
                    g_xcol[(size_t)(twv * 8 + c) * NSTOCK + n0 + nl + j] = tile[c][nl + j];
        }
    }
}

// ---------------------------------------------------------------------------
// Kernel A: exact descending rank. Density-matched monotone piecewise bins
// (peak occupancy ~1.56/bin), u32 histogram (atomic old = within-bin index),
// one prefix, atomic-free scatter, exact u64 in-bin scan, singleton fast path.
// ---------------------------------------------------------------------------
#define RT 512
#define HISTW 8196
#define SMEM_R (HISTW * 4 + NSTOCK * 8)

__device__ __forceinline__ unsigned int okey(float f) {
    unsigned int u = __float_as_uint(f);
    return (u & 0x80000000u) ? ~u : (u | 0x80000000u);
}

// monotone, continuous at exact-fp32 breakpoints -2.25,-1.25,1.25,2.25
__device__ __forceinline__ int binof(float v) {
    int b;
    if (v < -1.25f) {
        if (v < -2.25f) {
            b = __float2int_rd(fmaf(v, 256.0f, 1024.0f));        // [-4,-2.25): 448 bins
            b = b < 0 ? 0 : b;
        } else {
            b = 448 + __float2int_rd(fmaf(v, 1024.0f, 2304.0f)); // [-2.25,-1.25): 1024
        }
    } else if (v < 1.25f) {
        b = 1472 + __float2int_rd(fmaf(v, 2048.0f, 2560.0f));    // [-1.25,1.25): 5120
    } else if (v < 2.25f) {
        b = 6592 + __float2int_rd(fmaf(v, 1024.0f, -1280.0f));   // [1.25,2.25): 1024
    } else {
        b = 7616 + __float2int_rd(fmaf(v, 256.0f, -576.0f));     // [2.25,...): 576
        b = b > 8191 ? 8191 : b;
    }
    return b;
}

__global__ void __launch_bounds__(RT, 2) rank_kernel() {
    extern __shared__ unsigned char smem_raw[];
    unsigned int* hist = (unsigned int*)smem_raw;
    unsigned long long* pack = (unsigned long long*)(smem_raw + HISTW * 4);

    __shared__ unsigned int wsum[16];

    const int col = blockIdx.x;
    const int tid = threadIdx.x;
    const unsigned int lane = tid & 31u;
    const unsigned int wid  = tid >> 5;

    {
        uint4 z4 = make_uint4(0u, 0u, 0u, 0u);
        uint4* hv = (uint4*)hist;
#pragma unroll
        for (int i = 0; i < 4; i++) hv[tid + (i << 9)] = z4;
        if (tid == 0) { hist[8192] = 0u; hist[8193] = 0u; hist[8194] = 0u; hist[8195] = 0u; }
    }
    __syncthreads();

    const float* colp = g_xcol + (size_t)col * NSTOCK;

    // P1: coalesced loads, density bin, histogram atomic (old = index)
    unsigned int rk[16], lv[16];
#pragma unroll
    for (int i = 0; i < 16; i++) {
        int n = tid + (i << 9);
        if (n < NSTOCK) {
            float v = __ldg(colp + n);
            rk[i] = okey(v);
            int b = binof(v);
            unsigned int idx = atomicAdd(&hist[b], 1u);
            lv[i] = ((unsigned int)b << 16) | idx;
        }
    }
    __syncthreads();

    // exclusive prefix over 8192 u32 bins (16/thread via uint4)
    {
        uint4* hv = (uint4*)hist;
        uint4 a[4];
        unsigned int s = 0;
#pragma unroll
        for (int j = 0; j < 4; j++) {
            a[j] = hv[tid * 4 + j];
            s += a[j].x + a[j].y + a[j].z + a[j].w;
        }
        unsigned int v = s;
#pragma unroll
        for (int o = 1; o < 32; o <<= 1) {
            unsigned int t = __shfl_up_sync(0xFFFFFFFFu, v, o);
            if (lane >= (unsigned)o) v += t;
        }
        if (lane == 31u) wsum[wid] = v;
        __syncthreads();
        if (wid == 0) {
            unsigned int orig = (lane < 16u) ? wsum[lane] : 0u;
            unsigned int w = orig;
#pragma unroll
            for (int o = 1; o < 32; o <<= 1) {
                unsigned int t = __shfl_up_sync(0xFFFFFFFFu, w, o);
                if (lane >= (unsigned)o) w += t;
            }
            if (lane < 16u) wsum[lane] = w - orig;
        }
        __syncthreads();
        unsigned int run = wsum[wid] + (v - s);
#pragma unroll
        for (int j = 0; j < 4; j++) {
            unsigned int* p = &a[j].x;
#pragma unroll
            for (int k = 0; k < 4; k++) {
                unsigned int c = p[k];
                p[k] = run;
                run += c;
            }
            hv[tid * 4 + j] = a[j];
        }
        if (tid == 0) hist[8192] = (unsigned int)NSTOCK;
    }
    __syncthreads();

    // P3: scatter u64 tie-break keys (no atomics)
#pragma unroll
    for (int i = 0; i < 16; i++) {
        int n = tid + (i << 9);
        if (n < NSTOCK) {
            unsigned int b = lv[i] >> 16;
            unsigned int idx = lv[i] & 0xFFFFu;
            pack[hist[b] + idx] = ((unsigned long long)rk[i] << 13) | (8191u - (unsigned)n);
        }
    }
    __syncthreads();

    // P4: rank = above-segment + in-segment strictly-greater; coalesced store
    float* dst = g_rank + (size_t)col * NSTOCK;
#pragma unroll
    for (int i = 0; i < 16; i++) {
        int n = tid + (i << 9);
        if (n < NSTOCK) {
            unsigned int b = lv[i] >> 16;
            unsigned int start = hist[b];
            unsigned int end = hist[b + 1];
            unsigned int g = (unsigned int)NSTOCK - end;
            if (end - start > 1u) {
                unsigned long long K = ((unsigned long long)rk[i] << 13) | (8191u - (unsigned)n);
                for (unsigned int q = start; q < end; q++)
                    g += (pack[q] > K) ? 1u : 0u;
            }
            dst[n] = (float)g * (1.0f / (float)NSTOCK);
        }
    }
}

// ---------------------------------------------------------------------------
// Transpose [col][n] -> [n][col]
// ---------------------------------------------------------------------------
__global__ void transpose_kernel() {
    __shared__ float tile[32][33];
    const int c0 = blockIdx.x * 32;
    const int n0 = blockIdx.y * 32;
    const int tx = threadIdx.x, ty = threadIdx.y;
    tile[ty][tx] = g_rank[(size_t)(c0 + ty) * NSTOCK + n0 + tx];
    __syncthreads();
    g_rank_t[(size_t)(n0 + ty) * (WINDOW * EE) + c0 + tx] = tile[tx][ty];
}

// ---------------------------------------------------------------------------
// Kernel B: fused stats + conv (out-channel 127) + linear.
// Stats as 15+5 sub-chains; reduction = 1 shfl level + smem.
// ---------------------------------------------------------------------------
#define SID_STRIDE 328

__global__ void __launch_bounds__(320) main_kernel(
    const float* __restrict__ x,
    const float* __restrict__ conv_w,
    const float* __restrict__ conv_b,
    const float* __restrict__ lin_w,
    const float* __restrict__ lin_b,
    float* __restrict__ out)
{
    __shared__ __align__(16) float xe[59][8];
    __shared__ __align__(16) float stats[8 * SID_STRIDE];
    __shared__ __align__(16) float rank_row[WINDOW * EE];
    __shared__ float red[160][18];
    __shared__ float fin[LOUT];

    const int n = blockIdx.x;
    const int tid = threadIdx.x;
    const float* xn = x + (size_t)n * (TDIM * FDIM);

    if (tid < 118) {
        int row = tid >> 1, half = tid & 1;
        float4 v = *(const float4*)(xn + (5 + row) * FDIM + half * 4);
        *(float4*)(&xe[row][half * 4]) = v;
    }
    if (tid >= 128 && tid < 128 + (WINDOW * EE) / 4) {
        const float4* rsrc = (const float4*)(g_rank_t + (size_t)n * (WINDOW * EE));
        ((float4*)rank_row)[tid - 128] = rsrc[tid - 128];
    }
    __syncthreads();

    // stats: one (tw, ee) task per thread; 15+5 sub-chain merge
    {
        int tw = tid >> 3, ee = tid & 7;
        int r0 = tw;                         // xe row of window-20 start

        float s15 = 0.f, q15 = 0.f, mx15 = -1e30f, mn15 = 1e30f;
#pragma unroll
        for (int j = 0; j < 15; j++) {
            float v = xe[r0 + j][ee];
            s15 += v; q15 = fmaf(v, v, q15);
            mx15 = fmaxf(mx15, v); mn15 = fminf(mn15, v);
        }
        float s5 = 0.f, q5 = 0.f, mx5 = -1e30f, mn5 = 1e30f;
#pragma unroll
        for (int j = 15; j < 20; j++) {
            float v = xe[r0 + j][ee];
            s5 += v; q5 = fmaf(v, v, q5);
            mx5 = fmaxf(mx5, v); mn5 = fminf(mn5, v);
        }
        float s20 = s15 + s5, q20 = q15 + q5;
        float mx20 = fmaxf(mx15, mx5), mn20 = fminf(mn15, mn5);
        float m20 = s20 * 0.05f;
        float m5  = s5 * 0.2f;
        float sd20 = sqrtf(fmaxf(fmaf(-s20, m20, q20), 0.f) * (1.0f / 19.0f));
        float sd5  = sqrtf(fmaxf(fmaf(-s5, m5, q5), 0.f) * 0.25f);

        float* st = stats + tw * 8 + ee;
        st[0 * SID_STRIDE] = m5;   st[1 * SID_STRIDE] = sd5;
        st[2 * SID_STRIDE] = mx5;  st[3 * SID_STRIDE] = mn5;
        st[4 * SID_STRIDE] = m20;  st[5 * SID_STRIDE] = sd20;
        st[6 * SID_STRIDE] = mx20; st[7 * SID_STRIDE] = mn20;
    }
    __syncthreads();

    // conv: two threads per channel, each covering 18 of 36 outputs
    float acc[18];
#pragma unroll
    for (int j = 0; j < 18; j++) acc[j] = 0.f;

    const int hh = (tid >= 160) ? 1 : 0;
    const int c  = tid - hh * 160;
    const int l0 = hh * 18;

    if (c < INCH) {
        const float* wp = conv_w + 127 * (INCH * 5) + c * 5;
        float w0 = __ldg(wp + 0), w1 = __ldg(wp + 1), w2 = __ldg(wp + 2),
              w3 = __ldg(wp + 3), w4 = __ldg(wp + 4);

        if (c < FDIM) {
            const float* src = xn + (24 + l0) * FDIM + c;
#pragma unroll
            for (int tt = 0; tt < 22; tt++) {
                float v = __ldg(src + tt * FDIM);
#pragma unroll
                for (int k = 0; k < 5; k++) {
                    int j = tt - k;
                    if (j >= 0 && j < 18) {
                        float wk = (k == 0) ? w0 : (k == 1) ? w1 : (k == 2) ? w2 : (k == 3) ? w3 : w4;
                        acc[j] += v * wk;
                    }
                }
            }
        } else {
            int cc = c - FDIM;
            int grp = (cc >= 40) ? 1 : 0;
            int r = cc - grp * 40;
            int se = r >> 3;
            int ee = r & 7;
            const float* s_src;
            if (se == 2) {
                s_src = rank_row + ee;
            } else {
                int statid = (se < 2 ? se : se - 1) + grp * 4;
                s_src = stats + statid * SID_STRIDE + ee;
            }
            s_src += l0 * 8;
#pragma unroll
            for (int tt = 0; tt < 22; tt++) {
                float v = s_src[tt * 8];
#pragma unroll
                for (int k = 0; k < 5; k++) {
                    int j = tt - k;
                    if (j >= 0 && j < 18) {
                        float wk = (k == 0) ? w0 : (k == 1) ? w1 : (k == 2) ? w2 : (k == 3) ? w3 : w4;
                        acc[j] += v * wk;
                    }
                }
            }
        }
    }

    // 1-level butterfly (xor16) -> 16 partials/warp -> smem -> 36-thread finish
#pragma unroll
    for (int j = 0; j < 18; j++)
        acc[j] += __shfl_xor_sync(0xFFFFFFFFu, acc[j], 16);
    {
        const int w = tid >> 5;
        if ((tid & 31) < 16) {
#pragma unroll
            for (int j = 0; j < 18; j++) red[w * 16 + (tid & 15)][j] = acc[j];
        }
    }
    __syncthreads();

    if (tid < LOUT) {
        int h2 = (tid >= 18) ? 1 : 0;
        int j = tid - h2 * 18;
        const float* rp = &red[h2 * 80][j];
        float s = __ldg(conv_b + 127);
#pragma unroll
        for (int i = 0; i < 80; i++) s += rp[i * 18];
        float hv = (s >= 0.f) ? s : 0.01f * s;
        fin[tid] = hv * __ldg(lin_w + tid);
    }
    __syncthreads();

    if (tid == 0) {
        float s = __ldg(lin_b);
        for (int l = 0; l < LOUT; l++) s += fin[l];
        out[n] = s;
    }
}

// ---------------------------------------------------------------------------
extern "C" void kernel_launch(void* const* d_in, const int* in_sizes, int n_in,
                              void* d_out, int out_size) {
    const float* x      = (const float*)d_in[0];
    const float* conv_w = (const float*)d_in[1];
    const float* conv_b = (const float*)d_in[2];
    const float* lin_w  = (const float*)d_in[3];
    const float* lin_b  = (const float*)d_in[4];
    float* out = (float*)d_out;

    cudaFuncSetAttribute(rank_kernel, cudaFuncAttributeMaxDynamicSharedMemorySize, SMEM_R);

    gather_kernel<<<dim3(WINDOW, (NSTOCK + 127) / 128), 256>>>(x);
    rank_kernel<<<WINDOW * EE, RT, SMEM_R>>>();
    transpose_kernel<<<dim3((WINDOW * EE) / 32, NSTOCK / 32), dim3(32, 32)>>>();
    main_kernel<<<NSTOCK, 320>>>(x, conv_w, conv_b, lin_w, lin_b, out);
}

// round 14
// speedup vs baseline: 1.0707x; 1.0707x over previous
#include <cuda_runtime.h>
#include <cstdint>

#define WINDOW 40
#define EE 8
#define NSTOCK 8000
#define TDIM 64
#define FDIM 64
#define INCH 144
#define LOUT 36

__device__ float g_xcol[WINDOW * EE * NSTOCK];      // [col][n]  staged slice
__device__ float g_rank[WINDOW * EE * NSTOCK];      // [col][n]
__device__ float g_rank_t[NSTOCK * WINDOW * EE];    // [n][col]

// ---------------------------------------------------------------------------
// Gather: x[:, 24:64, 0:8] -> g_xcol[col][n], full sector efficiency.
// ---------------------------------------------------------------------------
__global__ void __launch_bounds__(256) gather_kernel(const float* __restrict__ x) {
    __shared__ float tile[8][128];
    const int twv = blockIdx.x;
    const int n0 = blockIdx.y * 128;
    const int t = threadIdx.x;

    {
        int nl = t >> 1, half = t & 1;
        int n = n0 + nl;
        if (n < NSTOCK) {
            float4 v = *(const float4*)(x + (size_t)n * (TDIM * FDIM) + (24 + twv) * FDIM + half * 4);
            tile[half * 4 + 0][nl] = v.x;
            tile[half * 4 + 1][nl] = v.y;
            tile[half * 4 + 2][nl] = v.z;
            tile[half * 4 + 3][nl] = v.w;
        }
    }
    __syncthreads();
    {
        int idx = t * 4;
        int c = idx >> 7, nl = idx & 127;
        if (n0 + nl + 3 < NSTOCK) {
            float4 v = *(const float4*)(&tile[c][nl]);
            *(float4*)(g_xcol + (size_t)(twv * 8 + c) * NSTOCK + n0 + nl) = v;
        } else {
            for (int j = 0; j < 4; j++)
                if (n0 + nl + j < NSTOCK)
                    g_xcol[(size_t)(twv * 8 + c) * NSTOCK + n0 + nl + j] = tile[c][nl + j];
        }
    }
}

// ---------------------------------------------------------------------------
// Kernel A (R12 proven version): exact descending rank, uniform value bins
// l2 = clamp(floor((v+4)*1024), 0, 8191). u32 histogram (atomic old = index),
// one prefix, atomic-free scatter, exact u64 in-bin scan, singleton fast path.
// ---------------------------------------------------------------------------
#define RT 512
#define HISTW 8196
#define SMEM_R (HISTW * 4 + NSTOCK * 8)

__device__ __forceinline__ unsigned int okey(float f) {
    unsigned int u = __float_as_uint(f);
    return (u & 0x80000000u) ? ~u : (u | 0x80000000u);
}

__global__ void __launch_bounds__(RT, 2) rank_kernel() {
    extern __shared__ unsigned char smem_raw[];
    unsigned int* hist = (unsigned int*)smem_raw;
    unsigned long long* pack = (unsigned long long*)(smem_raw + HISTW * 4);

    __shared__ unsigned int wsum[16];

    const int col = blockIdx.x;
    const int tid = threadIdx.x;
    const unsigned int lane = tid & 31u;
    const unsigned int wid  = tid >> 5;

    {
        uint4 z4 = make_uint4(0u, 0u, 0u, 0u);
        uint4* hv = (uint4*)hist;
#pragma unroll
        for (int i = 0; i < 4; i++) hv[tid + (i << 9)] = z4;
        if (tid == 0) { hist[8192] = 0u; hist[8193] = 0u; hist[8194] = 0u; hist[8195] = 0u; }
    }
    __syncthreads();

    const float* colp = g_xcol + (size_t)col * NSTOCK;

    unsigned int rk[16], lv[16];
#pragma unroll
    for (int i = 0; i < 16; i++) {
        int n = tid + (i << 9);
        if (n < NSTOCK) {
            float v = __ldg(colp + n);
            rk[i] = okey(v);
            int b = __float2int_rd(fmaf(v, 1024.0f, 4096.0f));
            b = (b < 0) ? 0 : (b > 8191 ? 8191 : b);
            unsigned int idx = atomicAdd(&hist[b], 1u);
            lv[i] = ((unsigned int)b << 16) | idx;
        }
    }
    __syncthreads();

    {
        uint4* hv = (uint4*)hist;
        uint4 a[4];
        unsigned int s = 0;
#pragma unroll
        for (int j = 0; j < 4; j++) {
            a[j] = hv[tid * 4 + j];
            s += a[j].x + a[j].y + a[j].z + a[j].w;
        }
        unsigned int v = s;
#pragma unroll
        for (int o = 1; o < 32; o <<= 1) {
            unsigned int t = __shfl_up_sync(0xFFFFFFFFu, v, o);
            if (lane >= (unsigned)o) v += t;
        }
        if (lane == 31u) wsum[wid] = v;
        __syncthreads();
        if (wid == 0) {
            unsigned int orig = (lane < 16u) ? wsum[lane] : 0u;
            unsigned int w = orig;
#pragma unroll
            for (int o = 1; o < 32; o <<= 1) {
                unsigned int t = __shfl_up_sync(0xFFFFFFFFu, w, o);
                if (lane >= (unsigned)o) w += t;
            }
            if (lane < 16u) wsum[lane] = w - orig;
        }
        __syncthreads();
        unsigned int run = wsum[wid] + (v - s);
#pragma unroll
        for (int j = 0; j < 4; j++) {
            unsigned int* p = &a[j].x;
#pragma unroll
            for (int k = 0; k < 4; k++) {
                unsigned int c = p[k];
                p[k] = run;
                run += c;
            }
            hv[tid * 4 + j] = a[j];
        }
        if (tid == 0) hist[8192] = (unsigned int)NSTOCK;
    }
    __syncthreads();

#pragma unroll
    for (int i = 0; i < 16; i++) {
        int n = tid + (i << 9);
        if (n < NSTOCK) {
            unsigned int b = lv[i] >> 16;
            unsigned int idx = lv[i] & 0xFFFFu;
            pack[hist[b] + idx] = ((unsigned long long)rk[i] << 13) | (8191u - (unsigned)n);
        }
    }
    __syncthreads();

    float* dst = g_rank + (size_t)col * NSTOCK;
#pragma unroll
    for (int i = 0; i < 16; i++) {
        int n = tid + (i << 9);
        if (n < NSTOCK) {
            unsigned int b = lv[i] >> 16;
            unsigned int start = hist[b];
            unsigned int end = hist[b + 1];
            unsigned int g = (unsigned int)NSTOCK - end;
            if (end - start > 1u) {
                unsigned long long K = ((unsigned long long)rk[i] << 13) | (8191u - (unsigned)n);
                for (unsigned int q = start; q < end; q++)
                    g += (pack[q] > K) ? 1u : 0u;
            }
            dst[n] = (float)g * (1.0f / (float)NSTOCK);
        }
    }
}

// ---------------------------------------------------------------------------
// Transpose [col][n] -> [n][col]
// ---------------------------------------------------------------------------
__global__ void transpose_kernel() {
    __shared__ float tile[32][33];
    const int c0 = blockIdx.x * 32;
    const int n0 = blockIdx.y * 32;
    const int tx = threadIdx.x, ty = threadIdx.y;
    tile[ty][tx] = g_rank[(size_t)(c0 + ty) * NSTOCK + n0 + tx];
    __syncthreads();
    g_rank_t[(size_t)(n0 + ty) * (WINDOW * EE) + c0 + tx] = tile[tx][ty];
}

// ---------------------------------------------------------------------------
// Kernel B: 2 samples per block (640 thr), named barriers per half.
// Per half: stats (15+5 chains) + conv (out-channel 127) + linear.
// ---------------------------------------------------------------------------
#define SID_STRIDE 328
#define HBAR(h) asm volatile("bar.sync %0, %1;" :: "r"((h) + 1), "r"(320) : "memory")

__global__ void __launch_bounds__(640) main_kernel(
    const float* __restrict__ x,
    const float* __restrict__ conv_w,
    const float* __restrict__ conv_b,
    const float* __restrict__ lin_w,
    const float* __restrict__ lin_b,
    float* __restrict__ out)
{
    __shared__ __align__(16) float xe[2][59][8];
    __shared__ __align__(16) float stats[2][8 * SID_STRIDE];
    __shared__ __align__(16) float rank_row[2][WINDOW * EE];
    __shared__ float red[2][160][18];
    __shared__ float fin[2][LOUT];

    const int tid_g = threadIdx.x;
    const int half = tid_g >= 320 ? 1 : 0;
    const int tid = tid_g - half * 320;
    const int n = blockIdx.x * 2 + half;
    const float* xn = x + (size_t)n * (TDIM * FDIM);

    if (tid < 118) {
        int row = tid >> 1, hq = tid & 1;
        float4 v = *(const float4*)(xn + (5 + row) * FDIM + hq * 4);
        *(float4*)(&xe[half][row][hq * 4]) = v;
    }
    if (tid >= 128 && tid < 128 + (WINDOW * EE) / 4) {
        const float4* rsrc = (const float4*)(g_rank_t + (size_t)n * (WINDOW * EE));
        ((float4*)rank_row[half])[tid - 128] = rsrc[tid - 128];
    }
    HBAR(half);

    // stats: one (tw, ee) task per thread; 15+5 sub-chain merge
    {
        int tw = tid >> 3, ee = tid & 7;

        float s15 = 0.f, q15 = 0.f, mx15 = -1e30f, mn15 = 1e30f;
#pragma unroll
        for (int j = 0; j < 15; j++) {
            float v = xe[half][tw + j][ee];
            s15 += v; q15 = fmaf(v, v, q15);
            mx15 = fmaxf(mx15, v); mn15 = fminf(mn15, v);
        }
        float s5 = 0.f, q5 = 0.f, mx5 = -1e30f, mn5 = 1e30f;
#pragma unroll
        for (int j = 15; j < 20; j++) {
            float v = xe[half][tw + j][ee];
            s5 += v; q5 = fmaf(v, v, q5);
            mx5 = fmaxf(mx5, v); mn5 = fminf(mn5, v);
        }
        float s20 = s15 + s5, q20 = q15 + q5;
        float mx20 = fmaxf(mx15, mx5), mn20 = fminf(mn15, mn5);
        float m20 = s20 * 0.05f;
        float m5  = s5 * 0.2f;
        float sd20 = sqrtf(fmaxf(fmaf(-s20, m20, q20), 0.f) * (1.0f / 19.0f));
        float sd5  = sqrtf(fmaxf(fmaf(-s5, m5, q5), 0.f) * 0.25f);

        float* st = stats[half] + tw * 8 + ee;
        st[0 * SID_STRIDE] = m5;   st[1 * SID_STRIDE] = sd5;
        st[2 * SID_STRIDE] = mx5;  st[3 * SID_STRIDE] = mn5;
        st[4 * SID_STRIDE] = m20;  st[5 * SID_STRIDE] = sd20;
        st[6 * SID_STRIDE] = mx20; st[7 * SID_STRIDE] = mn20;
    }
    HBAR(half);

    // conv: two threads per channel, each covering 18 of 36 outputs
    float acc[18];
#pragma unroll
    for (int j = 0; j < 18; j++) acc[j] = 0.f;

    const int hh = (tid >= 160) ? 1 : 0;
    const int c  = tid - hh * 160;
    const int l0 = hh * 18;

    if (c < INCH) {
        const float* wp = conv_w + 127 * (INCH * 5) + c * 5;
        float w0 = __ldg(wp + 0), w1 = __ldg(wp + 1), w2 = __ldg(wp + 2),
              w3 = __ldg(wp + 3), w4 = __ldg(wp + 4);

        if (c < FDIM) {
            const float* src = xn + (24 + l0) * FDIM + c;
#pragma unroll
            for (int tt = 0; tt < 22; tt++) {
                float v = __ldg(src + tt * FDIM);
#pragma unroll
                for (int k = 0; k < 5; k++) {
                    int j = tt - k;
                    if (j >= 0 && j < 18) {
                        float wk = (k == 0) ? w0 : (k == 1) ? w1 : (k == 2) ? w2 : (k == 3) ? w3 : w4;
                        acc[j] += v * wk;
                    }
                }
            }
        } else {
            int cc = c - FDIM;
            int grp = (cc >= 40) ? 1 : 0;
            int r = cc - grp * 40;
            int se = r >> 3;
            int ee = r & 7;
            const float* s_src;
            if (se == 2) {
                s_src = rank_row[half] + ee;
            } else {
                int statid = (se < 2 ? se : se - 1) + grp * 4;
                s_src = stats[half] + statid * SID_STRIDE + ee;
            }
            s_src += l0 * 8;
#pragma unroll
            for (int tt = 0; tt < 22; tt++) {
                float v = s_src[tt * 8];
#pragma unroll
                for (int k = 0; k < 5; k++) {
                    int j = tt - k;
                    if (j >= 0 && j < 18) {
                        float wk = (k == 0) ? w0 : (k == 1) ? w1 : (k == 2) ? w2 : (k == 3) ? w3 : w4;
                        acc[j] += v * wk;
                    }
                }
            }
        }
    }

    // 1-level butterfly (xor16) -> 16 partials/warp -> smem -> 36-thread finish
#pragma unroll
    for (int j = 0; j < 18; j++)
        acc[j] += __shfl_xor_sync(0xFFFFFFFFu, acc[j], 16);
    {
        const int w = tid >> 5;
        if ((tid & 31) < 16) {
#pragma unroll
            for (int j = 0; j < 18; j++) red[half][w * 16 + (tid & 15)][j] = acc[j];
        }
    }
    HBAR(half);

    if (tid < LOUT) {
        int h2 = (tid >= 18) ? 1 : 0;
        int j = tid - h2 * 18;
        const float* rp = &red[half][h2 * 80][j];
        float s = __ldg(conv_b + 127);
#pragma unroll
        for (int i = 0; i < 80; i++) s += rp[i * 18];
        float hv = (s >= 0.f) ? s : 0.01f * s;
        fin[half][tid] = hv * __ldg(lin_w + tid);
    }
    HBAR(half);

    if (tid == 0) {
        float s = __ldg(lin_b);
        for (int l = 0; l < LOUT; l++) s += fin[half][l];
        out[n] = s;
    }
}

// ---------------------------------------------------------------------------
extern "C" void kernel_launch(void* const* d_in, const int* in_sizes, int n_in,
                              void* d_out, int out_size) {
    const float* x      = (const float*)d_in[0];
    const float* conv_w = (const float*)d_in[1];
    const float* conv_b = (const float*)d_in[2];
    const float* lin_w  = (const float*)d_in[3];
    const float* lin_b  = (const float*)d_in[4];
    float* out = (float*)d_out;

    cudaFuncSetAttribute(rank_kernel, cudaFuncAttributeMaxDynamicSharedMemorySize, SMEM_R);

    gather_kernel<<<dim3(WINDOW, (NSTOCK + 127) / 128), 256>>>(x);
    rank_kernel<<<WINDOW * EE, RT, SMEM_R>>>();
    transpose_kernel<<<dim3((WINDOW * EE) / 32, NSTOCK / 32), dim3(32, 32)>>>();
    main_kernel<<<NSTOCK / 2, 640>>>(x, conv_w, conv_b, lin_w, lin_b, out);
}